// round 1
// baseline (speedup 1.0000x reference)
#include <cuda_runtime.h>
#include <math.h>

#define BB 32
#define SS 2048
#define FF 128
#define DK 32
#define NROWS (BB*SS)

// Scratch (static device globals; no runtime allocation)
__device__ float g_q[NROWS*DK];     // Q projection, pre-scaled by 1/sqrt(32)
__device__ float g_k[NROWS*DK];     // K projection
__device__ float g_vw[NROWS*3];     // v_in @ (Wv @ Wo_eff)  -- bias folded into g_cst
__device__ float g_wveff[FF*3];     // Wv @ Wo_eff
__device__ float g_cst[3];          // bo + bv . Wo_eff

// ---------------------------------------------------------------------------
// Prep: Wo_eff = sum over heads of Wo blocks; fold through Wv and biases.
// ---------------------------------------------------------------------------
__global__ void prep_kernel(const float* __restrict__ Wv, const float* __restrict__ bv,
                            const float* __restrict__ Wo, const float* __restrict__ bo) {
    __shared__ float sWoE[DK*3];
    int t = threadIdx.x;
    if (t < DK*3) {
        int d = t / 3, f = t - d*3;
        float s = 0.f;
        #pragma unroll
        for (int h = 0; h < 16; ++h) s += Wo[(h*DK + d)*3 + f];
        sWoE[t] = s;
    }
    __syncthreads();
    for (int idx = t; idx < FF*3; idx += blockDim.x) {
        int i = idx / 3, f = idx - i*3;
        float s = 0.f;
        #pragma unroll
        for (int d = 0; d < DK; ++d) s += Wv[i*DK + d] * sWoE[d*3 + f];
        g_wveff[idx] = s;
    }
    if (t < 3) {
        float s = bo[t];
        #pragma unroll
        for (int d = 0; d < DK; ++d) s += bv[d] * sWoE[d*3 + t];
        g_cst[t] = s;
    }
}

// ---------------------------------------------------------------------------
// Projections: each block handles 32 rows (flattened b*S+s).
//   g_q = (q_in@Wq + bq) * 1/sqrt(32),  g_k = k_in@Wk + bk,
//   g_vw = v_in @ Wv_eff   (bias folded into g_cst)
// ---------------------------------------------------------------------------
__global__ __launch_bounds__(256) void proj_kernel(
    const float* __restrict__ qin, const float* __restrict__ kin, const float* __restrict__ vin,
    const float* __restrict__ Wq, const float* __restrict__ bq,
    const float* __restrict__ Wk, const float* __restrict__ bk) {
    __shared__ float sW[FF*DK];     // 16 KB
    __shared__ float sIn[32*FF];    // 16 KB
    __shared__ float sWv[FF*3];
    const int tid  = threadIdx.x;
    const int lane = tid & 31;      // output column
    const int wr   = tid >> 5;      // 8 warps -> 4 rows each
    const size_t row0 = (size_t)blockIdx.x * 32;

    // ---------------- Q ----------------
    for (int i = tid; i < FF*DK; i += 256) sW[i] = Wq[i];
    for (int i = tid; i < 1024; i += 256)
        ((float4*)sIn)[i] = ((const float4*)qin)[row0*32 + i];
    __syncthreads();
    {
        const float bb = bq[lane];
        const int r = wr*4;
        float a0=0.f,a1=0.f,a2=0.f,a3=0.f;
        #pragma unroll 4
        for (int f = 0; f < FF; ++f) {
            float w = sW[f*DK + lane];
            a0 = fmaf(sIn[(r+0)*FF+f], w, a0);
            a1 = fmaf(sIn[(r+1)*FF+f], w, a1);
            a2 = fmaf(sIn[(r+2)*FF+f], w, a2);
            a3 = fmaf(sIn[(r+3)*FF+f], w, a3);
        }
        const float qs = 0.17677669529663687f;   // 1/sqrt(32)
        g_q[(row0+r+0)*DK + lane] = (a0 + bb) * qs;
        g_q[(row0+r+1)*DK + lane] = (a1 + bb) * qs;
        g_q[(row0+r+2)*DK + lane] = (a2 + bb) * qs;
        g_q[(row0+r+3)*DK + lane] = (a3 + bb) * qs;
    }
    __syncthreads();

    // ---------------- K ----------------
    for (int i = tid; i < FF*DK; i += 256) sW[i] = Wk[i];
    for (int i = tid; i < 1024; i += 256)
        ((float4*)sIn)[i] = ((const float4*)kin)[row0*32 + i];
    __syncthreads();
    {
        const float bb = bk[lane];
        const int r = wr*4;
        float a0=0.f,a1=0.f,a2=0.f,a3=0.f;
        #pragma unroll 4
        for (int f = 0; f < FF; ++f) {
            float w = sW[f*DK + lane];
            a0 = fmaf(sIn[(r+0)*FF+f], w, a0);
            a1 = fmaf(sIn[(r+1)*FF+f], w, a1);
            a2 = fmaf(sIn[(r+2)*FF+f], w, a2);
            a3 = fmaf(sIn[(r+3)*FF+f], w, a3);
        }
        g_k[(row0+r+0)*DK + lane] = a0 + bb;
        g_k[(row0+r+1)*DK + lane] = a1 + bb;
        g_k[(row0+r+2)*DK + lane] = a2 + bb;
        g_k[(row0+r+3)*DK + lane] = a3 + bb;
    }
    __syncthreads();

    // ---------------- VW (3 cols) ----------------
    for (int i = tid; i < FF*3; i += 256) sWv[i] = g_wveff[i];
    for (int i = tid; i < 1024; i += 256)
        ((float4*)sIn)[i] = ((const float4*)vin)[row0*32 + i];
    __syncthreads();
    if (tid < 96) {
        int r = tid / 3, f = tid - r*3;
        float s0=0.f,s1=0.f,s2=0.f,s3=0.f;
        #pragma unroll 8
        for (int ff = 0; ff < FF; ff += 4) {
            s0 = fmaf(sIn[r*FF+ff+0], sWv[(ff+0)*3+f], s0);
            s1 = fmaf(sIn[r*FF+ff+1], sWv[(ff+1)*3+f], s1);
            s2 = fmaf(sIn[r*FF+ff+2], sWv[(ff+2)*3+f], s2);
            s3 = fmaf(sIn[r*FF+ff+3], sWv[(ff+3)*3+f], s3);
        }
        g_vw[(row0+r)*3 + f] = (s0+s1)+(s2+s3);
    }
}

// ---------------------------------------------------------------------------
// Flash attention: block = (q-tile of 64, batch). 256 threads as 16x16 grid,
// each thread owns a 4x4 score tile. K tile XOR-swizzled for conflict-free
// LDS.128. Online softmax; 3-column output accumulator (vw already includes
// Wo_eff).
// ---------------------------------------------------------------------------
__global__ __launch_bounds__(256) void flash_kernel(float* __restrict__ out) {
    __shared__ float sQ[64*36];     // padded rows (36 floats) -> conflict-free
    __shared__ float sK[64*32];     // xor-swizzled per 16B group
    __shared__ float sVW[192];
    const int tid = threadIdx.x;
    const int ty = tid >> 4, tx = tid & 15;
    const int r4 = ty*4, c4 = tx*4;
    const size_t base = (size_t)blockIdx.y * SS;
    const int q0 = blockIdx.x * 64;

    // Load Q tile once
    for (int i = tid; i < 512; i += 256) {
        int r = i >> 3, seg = i & 7;
        *(float4*)&sQ[r*36 + seg*4] = *(const float4*)&g_q[(base + q0 + r)*DK + seg*4];
    }

    float m[4], l[4], acc[4][3];
    #pragma unroll
    for (int i = 0; i < 4; ++i) {
        m[i] = -1e30f; l[i] = 0.f;
        acc[i][0] = acc[i][1] = acc[i][2] = 0.f;
    }

    for (int k0 = 0; k0 < SS; k0 += 64) {
        __syncthreads();   // protect sK/sVW reuse
        for (int i = tid; i < 512; i += 256) {
            int r = i >> 3, seg = i & 7;
            float4 v = *(const float4*)&g_k[(base + k0 + r)*DK + seg*4];
            int grp = (seg ^ (r >> 2)) & 7;
            *(float4*)&sK[r*32 + grp*4] = v;
        }
        if (tid < 192) sVW[tid] = g_vw[(base + k0)*3 + tid];
        __syncthreads();

        // ---- scores: 4x4 per thread, d vectorized by float4 ----
        float s[4][4];
        #pragma unroll
        for (int i = 0; i < 4; ++i)
            #pragma unroll
            for (int j = 0; j < 4; ++j) s[i][j] = 0.f;

        #pragma unroll
        for (int d4 = 0; d4 < 8; ++d4) {
            float4 a[4], bv4[4];
            #pragma unroll
            for (int i = 0; i < 4; ++i)
                a[i] = *(float4*)&sQ[(r4+i)*36 + d4*4];
            const int grp = ((d4 ^ tx) & 7) * 4;
            #pragma unroll
            for (int j = 0; j < 4; ++j)
                bv4[j] = *(float4*)&sK[(c4+j)*32 + grp];
            #pragma unroll
            for (int i = 0; i < 4; ++i)
                #pragma unroll
                for (int j = 0; j < 4; ++j) {
                    s[i][j] = fmaf(a[i].x, bv4[j].x, s[i][j]);
                    s[i][j] = fmaf(a[i].y, bv4[j].y, s[i][j]);
                    s[i][j] = fmaf(a[i].z, bv4[j].z, s[i][j]);
                    s[i][j] = fmaf(a[i].w, bv4[j].w, s[i][j]);
                }
        }

        // vw values for this thread's 4 key columns
        float vw[4][3];
        #pragma unroll
        for (int j = 0; j < 4; ++j) {
            vw[j][0] = sVW[(c4+j)*3 + 0];
            vw[j][1] = sVW[(c4+j)*3 + 1];
            vw[j][2] = sVW[(c4+j)*3 + 2];
        }

        // ---- online softmax update ----
        #pragma unroll
        for (int i = 0; i < 4; ++i) {
            float tm = fmaxf(fmaxf(s[i][0], s[i][1]), fmaxf(s[i][2], s[i][3]));
            tm = fmaxf(tm, __shfl_xor_sync(0xffffffffu, tm, 1));
            tm = fmaxf(tm, __shfl_xor_sync(0xffffffffu, tm, 2));
            tm = fmaxf(tm, __shfl_xor_sync(0xffffffffu, tm, 4));
            tm = fmaxf(tm, __shfl_xor_sync(0xffffffffu, tm, 8));
            float mn = fmaxf(m[i], tm);
            float sc = __expf(m[i] - mn);
            m[i] = mn;
            float p0 = __expf(s[i][0] - mn);
            float p1 = __expf(s[i][1] - mn);
            float p2 = __expf(s[i][2] - mn);
            float p3 = __expf(s[i][3] - mn);
            l[i] = l[i]*sc + ((p0+p1)+(p2+p3));
            acc[i][0] = acc[i][0]*sc + (fmaf(p0,vw[0][0],fmaf(p1,vw[1][0],fmaf(p2,vw[2][0],p3*vw[3][0]))));
            acc[i][1] = acc[i][1]*sc + (fmaf(p0,vw[0][1],fmaf(p1,vw[1][1],fmaf(p2,vw[2][1],p3*vw[3][1]))));
            acc[i][2] = acc[i][2]*sc + (fmaf(p0,vw[0][2],fmaf(p1,vw[1][2],fmaf(p2,vw[2][2],p3*vw[3][2]))));
        }
    }

    // ---- reduce across the 16 tx lanes (within half-warps) ----
    #pragma unroll
    for (int i = 0; i < 4; ++i) {
        #pragma unroll
        for (int o = 8; o > 0; o >>= 1) {
            l[i]      += __shfl_xor_sync(0xffffffffu, l[i], o);
            acc[i][0] += __shfl_xor_sync(0xffffffffu, acc[i][0], o);
            acc[i][1] += __shfl_xor_sync(0xffffffffu, acc[i][1], o);
            acc[i][2] += __shfl_xor_sync(0xffffffffu, acc[i][2], o);
        }
    }
    if (tx == 0) {
        const float c0 = g_cst[0], c1 = g_cst[1], c2 = g_cst[2];
        #pragma unroll
        for (int i = 0; i < 4; ++i) {
            size_t orow = base + q0 + r4 + i;
            float inv = 1.0f / l[i];
            out[orow*3 + 0] = fmaf(acc[i][0], inv, c0);
            out[orow*3 + 1] = fmaf(acc[i][1], inv, c1);
            out[orow*3 + 2] = fmaf(acc[i][2], inv, c2);
        }
    }
}

extern "C" void kernel_launch(void* const* d_in, const int* in_sizes, int n_in,
                              void* d_out, int out_size) {
    const float* qin = (const float*)d_in[0];
    const float* kin = (const float*)d_in[1];
    const float* vin = (const float*)d_in[2];
    const float* Wq  = (const float*)d_in[3];
    const float* bq  = (const float*)d_in[4];
    const float* Wk  = (const float*)d_in[5];
    const float* bk  = (const float*)d_in[6];
    const float* Wv  = (const float*)d_in[7];
    const float* bv  = (const float*)d_in[8];
    const float* Wo  = (const float*)d_in[9];
    const float* bo  = (const float*)d_in[10];
    float* out = (float*)d_out;

    prep_kernel<<<1, 128>>>(Wv, bv, Wo, bo);
    proj_kernel<<<NROWS/32, 256>>>(qin, kin, vin, Wq, bq, Wk, bk);
    flash_kernel<<<dim3(SS/64, BB), 256>>>(out);
}

// round 3
// speedup vs baseline: 1.8852x; 1.8852x over previous
#include <cuda_runtime.h>
#include <cuda_bf16.h>
#include <math.h>
#include <cstdint>

#define BB 32
#define SS 2048
#define FF 128
#define DK 32
#define NROWS (BB*SS)

// Packed projections, 96 bf16 per row (192B):
//   g_qp row = [q_hi(32) | q_hi(32) | q_lo(32)]   (q pre-scaled by 1/sqrt(32))
//   g_kp row = [k_hi(32) | k_lo(32) | k_hi(32)]
// => dot(A_row, B_row) = qh.kh + qh.kl + ql.kh  (3-term bf16 split, err ~1e-5)
__device__ __nv_bfloat16 g_qp[NROWS*96];
__device__ __nv_bfloat16 g_kp[NROWS*96];
__device__ float g_vw[NROWS*4];            // v_in @ (Wv @ Wo_eff), padded to 4

static __device__ __forceinline__ uint32_t smem_u32(const void* p) {
    uint32_t a;
    asm("{ .reg .u64 t; cvta.to.shared.u64 t, %1; cvt.u32.u64 %0, t; }" : "=r"(a) : "l"(p));
    return a;
}

#define LDSM_X4(r0,r1,r2,r3,addr) \
    asm volatile("ldmatrix.sync.aligned.m8n8.x4.shared.b16 {%0,%1,%2,%3}, [%4];" \
        : "=r"(r0), "=r"(r1), "=r"(r2), "=r"(r3) : "r"(addr))

#define MMA16816(c0,c1,c2,c3,a0,a1,a2,a3,b0,b1) \
    asm volatile("mma.sync.aligned.m16n8k16.row.col.f32.bf16.bf16.f32 " \
        "{%0,%1,%2,%3}, {%4,%5,%6,%7}, {%8,%9}, {%0,%1,%2,%3};" \
        : "+f"(c0), "+f"(c1), "+f"(c2), "+f"(c3) \
        : "r"(a0), "r"(a1), "r"(a2), "r"(a3), "r"(b0), "r"(b1))

// ---------------------------------------------------------------------------
// Projection kernel: 32 rows per block; folds Wo_eff into Wv per-block.
// ---------------------------------------------------------------------------
__global__ __launch_bounds__(256) void proj_kernel(
    const float* __restrict__ qin, const float* __restrict__ kin, const float* __restrict__ vin,
    const float* __restrict__ Wq, const float* __restrict__ bq,
    const float* __restrict__ Wk, const float* __restrict__ bk,
    const float* __restrict__ Wv, const float* __restrict__ Wo) {
    __shared__ float sW[FF*DK];
    __shared__ float sIn[32*FF];
    __shared__ float sWoE[DK*3];
    __shared__ float sWv[FF*3];
    const int tid  = threadIdx.x;
    const int lane = tid & 31;
    const int wr   = tid >> 5;
    const size_t row0 = (size_t)blockIdx.x * 32;

    if (tid < 96) {
        int d = tid / 3, f = tid - d*3;
        float s = 0.f;
        #pragma unroll
        for (int h = 0; h < 16; ++h) s += Wo[(h*DK + d)*3 + f];
        sWoE[tid] = s;
    }
    __syncthreads();
    for (int i = tid; i < FF*3; i += 256) {
        int r = i / 3, f = i - r*3;
        float s = 0.f;
        #pragma unroll
        for (int d = 0; d < DK; ++d) s = fmaf(Wv[r*DK + d], sWoE[d*3 + f], s);
        sWv[i] = s;
    }

    // ---------------- Q ----------------
    for (int i = tid; i < FF*DK; i += 256) sW[i] = Wq[i];
    for (int i = tid; i < 1024; i += 256)
        ((float4*)sIn)[i] = ((const float4*)qin)[row0*32 + i];
    __syncthreads();
    {
        const float bb = bq[lane];
        const int r = wr*4;
        float a0=0.f,a1=0.f,a2=0.f,a3=0.f;
        #pragma unroll 4
        for (int f = 0; f < FF; ++f) {
            float w = sW[f*DK + lane];
            a0 = fmaf(sIn[(r+0)*FF+f], w, a0);
            a1 = fmaf(sIn[(r+1)*FF+f], w, a1);
            a2 = fmaf(sIn[(r+2)*FF+f], w, a2);
            a3 = fmaf(sIn[(r+3)*FF+f], w, a3);
        }
        const float qs = 0.17677669529663687f;   // 1/sqrt(32)
        #pragma unroll
        for (int i = 0; i < 4; ++i) {
            float v = ((i==0)?a0:(i==1)?a1:(i==2)?a2:a3);
            v = (v + bb) * qs;
            __nv_bfloat16 h = __float2bfloat16(v);
            __nv_bfloat16 lo = __float2bfloat16(v - __bfloat162float(h));
            size_t rr = row0 + r + i;
            g_qp[rr*96 + lane]      = h;
            g_qp[rr*96 + 32 + lane] = h;
            g_qp[rr*96 + 64 + lane] = lo;
        }
    }
    __syncthreads();

    // ---------------- K ----------------
    for (int i = tid; i < FF*DK; i += 256) sW[i] = Wk[i];
    for (int i = tid; i < 1024; i += 256)
        ((float4*)sIn)[i] = ((const float4*)kin)[row0*32 + i];
    __syncthreads();
    {
        const float bb = bk[lane];
        const int r = wr*4;
        float a0=0.f,a1=0.f,a2=0.f,a3=0.f;
        #pragma unroll 4
        for (int f = 0; f < FF; ++f) {
            float w = sW[f*DK + lane];
            a0 = fmaf(sIn[(r+0)*FF+f], w, a0);
            a1 = fmaf(sIn[(r+1)*FF+f], w, a1);
            a2 = fmaf(sIn[(r+2)*FF+f], w, a2);
            a3 = fmaf(sIn[(r+3)*FF+f], w, a3);
        }
        #pragma unroll
        for (int i = 0; i < 4; ++i) {
            float v = ((i==0)?a0:(i==1)?a1:(i==2)?a2:a3) + bb;
            __nv_bfloat16 h = __float2bfloat16(v);
            __nv_bfloat16 lo = __float2bfloat16(v - __bfloat162float(h));
            size_t rr = row0 + r + i;
            g_kp[rr*96 + lane]      = h;
            g_kp[rr*96 + 32 + lane] = lo;
            g_kp[rr*96 + 64 + lane] = h;
        }
    }
    __syncthreads();

    // ---------------- VW (3 cols, padded to 4) ----------------
    for (int i = tid; i < 1024; i += 256)
        ((float4*)sIn)[i] = ((const float4*)vin)[row0*32 + i];
    __syncthreads();
    if (tid < 96) {
        int r = tid / 3, f = tid - r*3;
        float s0=0.f,s1=0.f,s2=0.f,s3=0.f;
        #pragma unroll 8
        for (int ff = 0; ff < FF; ff += 4) {
            s0 = fmaf(sIn[r*FF+ff+0], sWv[(ff+0)*3+f], s0);
            s1 = fmaf(sIn[r*FF+ff+1], sWv[(ff+1)*3+f], s1);
            s2 = fmaf(sIn[r*FF+ff+2], sWv[(ff+2)*3+f], s2);
            s3 = fmaf(sIn[r*FF+ff+3], sWv[(ff+3)*3+f], s3);
        }
        g_vw[(row0+r)*4 + f] = (s0+s1)+(s2+s3);
    }
}

// ---------------------------------------------------------------------------
// Flash kernel: HMMA bf16 (mma.sync m16n8k16), K=96 combined split-GEMM.
// Block = (q-tile of 128, batch). 8 warps; warp w owns q rows [w*16, w*16+16).
// No-max softmax (scores bounded), fused 3-col PV via vw.
// ---------------------------------------------------------------------------
#define RSTR 208                       // smem row stride bytes (13*16, odd -> conflict-free LDSM)
#define SQ_OFF 0
#define SK_OFF (128*RSTR)              // 26624
#define VW_OFF (2*128*RSTR)            // 53248
#define CST_OFF (VW_OFF + 2048)        // 55296
#define SMEM_BYTES (CST_OFF + 16)      // 55312

__global__ __launch_bounds__(256)
void flash3_kernel(float* __restrict__ out,
                   const float* __restrict__ bv,
                   const float* __restrict__ Wo,
                   const float* __restrict__ bo) {
    extern __shared__ __align__(16) unsigned char smem[];
    float* sVW  = (float*)(smem + VW_OFF);
    float* sCST = (float*)(smem + CST_OFF);
    const int tid  = threadIdx.x;
    const int wid  = tid >> 5, lane = tid & 31;
    const size_t base = (size_t)blockIdx.y * SS;
    const int q0 = blockIdx.x * 128;
    const uint32_t sbase = smem_u32(smem);

    // output constant: bo + bv . Wo_eff
    if (tid < 3) {
        float s = bo[tid];
        #pragma unroll
        for (int d = 0; d < DK; ++d) {
            float w = 0.f;
            #pragma unroll
            for (int h = 0; h < 16; ++h) w += Wo[(h*DK + d)*3 + tid];
            s = fmaf(bv[d], w, s);
        }
        sCST[tid] = s;
    }

    // Load Q tile: 128 rows x 192B -> stride 208
    for (int i = tid; i < 1536; i += 256) {
        int rr = i / 12, sg = i - rr*12;
        *(uint4*)(smem + SQ_OFF + rr*RSTR + sg*16) =
            *(const uint4*)((const unsigned char*)g_qp + (base + q0 + rr)*192 + sg*16);
    }
    __syncthreads();

    // Preload per-warp A fragments (loop-invariant): 6 k-steps x 4 regs
    const int lr  = lane & 7;
    const int sel = lane >> 3;
    uint32_t aF[6][4];
    {
        int arow = wid*16 + lr + (sel & 1)*8;
        uint32_t abase = sbase + SQ_OFF + arow*RSTR + (sel >> 1)*16;
        #pragma unroll
        for (int g = 0; g < 6; ++g)
            LDSM_X4(aF[g][0], aF[g][1], aF[g][2], aF[g][3], abase + g*32);
    }

    // accumulators: rows r0 = wid*16 + lane/4, r1 = r0 + 8
    float l0 = 0.f, l1 = 0.f;
    float A0x=0.f, A0y=0.f, A0z=0.f, A1x=0.f, A1y=0.f, A1z=0.f;
    const int qc = (lane & 3)*2;           // col within n-tile

    for (int t = 0; t < 16; ++t) {
        const size_t kbase = base + (size_t)t * 128;
        __syncthreads();   // protect previous iteration's sK/sVW reads
        for (int i = tid; i < 1536; i += 256) {
            int rr = i / 12, sg = i - rr*12;
            *(uint4*)(smem + SK_OFF + rr*RSTR + sg*16) =
                *(const uint4*)((const unsigned char*)g_kp + (kbase + rr)*192 + sg*16);
        }
        if (tid < 128)
            ((float4*)sVW)[tid] = ((const float4*)g_vw)[kbase + tid];
        __syncthreads();

        #pragma unroll
        for (int j = 0; j < 16; ++j) {     // n-tiles of 8 key columns
            int krow = j*8 + lr;
            uint32_t bbase = sbase + SK_OFF + krow*RSTR + sel*16;
            uint32_t bF[12];
            LDSM_X4(bF[0], bF[1], bF[2],  bF[3],  bbase);        // k-steps 0,1
            LDSM_X4(bF[4], bF[5], bF[6],  bF[7],  bbase + 64);   // k-steps 2,3
            LDSM_X4(bF[8], bF[9], bF[10], bF[11], bbase + 128);  // k-steps 4,5

            float c0=0.f, c1=0.f, c2=0.f, c3=0.f;
            #pragma unroll
            for (int s = 0; s < 6; ++s)
                MMA16816(c0, c1, c2, c3,
                         aF[s][0], aF[s][1], aF[s][2], aF[s][3],
                         bF[2*s], bF[2*s+1]);

            // epilogue: exp + fused 3-col PV
            float p0 = __expf(c0), p1 = __expf(c1);
            float p2 = __expf(c2), p3 = __expf(c3);
            float4 va = *(float4*)&sVW[(j*8 + qc)*4];
            float4 vb = *(float4*)&sVW[(j*8 + qc + 1)*4];
            l0 += p0 + p1;  l1 += p2 + p3;
            A0x = fmaf(p0, va.x, fmaf(p1, vb.x, A0x));
            A0y = fmaf(p0, va.y, fmaf(p1, vb.y, A0y));
            A0z = fmaf(p0, va.z, fmaf(p1, vb.z, A0z));
            A1x = fmaf(p2, va.x, fmaf(p3, vb.x, A1x));
            A1y = fmaf(p2, va.y, fmaf(p3, vb.y, A1y));
            A1z = fmaf(p2, va.z, fmaf(p3, vb.z, A1z));
        }
    }

    // reduce across the 4 lanes of each quad (they share q-rows)
    #pragma unroll
    for (int o = 1; o <= 2; o <<= 1) {
        l0  += __shfl_xor_sync(0xffffffffu, l0,  o);
        l1  += __shfl_xor_sync(0xffffffffu, l1,  o);
        A0x += __shfl_xor_sync(0xffffffffu, A0x, o);
        A0y += __shfl_xor_sync(0xffffffffu, A0y, o);
        A0z += __shfl_xor_sync(0xffffffffu, A0z, o);
        A1x += __shfl_xor_sync(0xffffffffu, A1x, o);
        A1y += __shfl_xor_sync(0xffffffffu, A1y, o);
        A1z += __shfl_xor_sync(0xffffffffu, A1z, o);
    }
    if ((lane & 3) == 0) {
        const float c0 = sCST[0], c1 = sCST[1], c2 = sCST[2];
        size_t r0 = base + q0 + wid*16 + (lane >> 2);
        float inv0 = 1.0f / l0;
        out[r0*3 + 0] = fmaf(A0x, inv0, c0);
        out[r0*3 + 1] = fmaf(A0y, inv0, c1);
        out[r0*3 + 2] = fmaf(A0z, inv0, c2);
        size_t r1 = r0 + 8;
        float inv1 = 1.0f / l1;
        out[r1*3 + 0] = fmaf(A1x, inv1, c0);
        out[r1*3 + 1] = fmaf(A1y, inv1, c1);
        out[r1*3 + 2] = fmaf(A1z, inv1, c2);
    }
}

extern "C" void kernel_launch(void* const* d_in, const int* in_sizes, int n_in,
                              void* d_out, int out_size) {
    const float* qin = (const float*)d_in[0];
    const float* kin = (const float*)d_in[1];
    const float* vin = (const float*)d_in[2];
    const float* Wq  = (const float*)d_in[3];
    const float* bq  = (const float*)d_in[4];
    const float* Wk  = (const float*)d_in[5];
    const float* bk  = (const float*)d_in[6];
    const float* Wv  = (const float*)d_in[7];
    const float* bv  = (const float*)d_in[8];
    const float* Wo  = (const float*)d_in[9];
    const float* bo  = (const float*)d_in[10];
    float* out = (float*)d_out;

    cudaFuncSetAttribute(flash3_kernel,
                         cudaFuncAttributeMaxDynamicSharedMemorySize, SMEM_BYTES);
    proj_kernel<<<NROWS/32, 256>>>(qin, kin, vin, Wq, bq, Wk, bk, Wv, Wo);
    flash3_kernel<<<dim3(SS/128, BB), 256, SMEM_BYTES>>>(out, bv, Wo, bo);
}

// round 4
// speedup vs baseline: 2.1290x; 1.1294x over previous
#include <cuda_runtime.h>
#include <cuda_bf16.h>
#include <math.h>
#include <cstdint>

#define BB 32
#define SS 2048
#define FF 128
#define DK 32
#define NROWS (BB*SS)

// Packed projections, 96 bf16 per row (192B):
//   g_qp row = [q_hi(32) | q_hi(32) | q_lo(32)]   (q pre-scaled by 1/sqrt(32))
//   g_kp row = [k_hi(32) | k_lo(32) | k_hi(32)]
// => dot(A_row, B_row) = qh.kh + qh.kl + ql.kh  (3-term bf16 split)
__device__ __nv_bfloat16 g_qp[NROWS*96];
__device__ __nv_bfloat16 g_kp[NROWS*96];
__device__ float g_vw[NROWS*4];            // v_in @ (Wv @ Wo_eff), padded to 4

static __device__ __forceinline__ uint32_t smem_u32(const void* p) {
    uint32_t a;
    asm("{ .reg .u64 t; cvta.to.shared.u64 t, %1; cvt.u32.u64 %0, t; }" : "=r"(a) : "l"(p));
    return a;
}

#define LDSM_X4(r0,r1,r2,r3,addr) \
    asm volatile("ldmatrix.sync.aligned.m8n8.x4.shared.b16 {%0,%1,%2,%3}, [%4];" \
        : "=r"(r0), "=r"(r1), "=r"(r2), "=r"(r3) : "r"(addr))

#define MMA16816(c0,c1,c2,c3,a0,a1,a2,a3,b0,b1) \
    asm volatile("mma.sync.aligned.m16n8k16.row.col.f32.bf16.bf16.f32 " \
        "{%0,%1,%2,%3}, {%4,%5,%6,%7}, {%8,%9}, {%0,%1,%2,%3};" \
        : "+f"(c0), "+f"(c1), "+f"(c2), "+f"(c3) \
        : "r"(a0), "r"(a1), "r"(a2), "r"(a3), "r"(b0), "r"(b1))

// ---------------------------------------------------------------------------
// Projection kernel: 64 rows per block, 8 rows per thread register-blocked.
// ---------------------------------------------------------------------------
__global__ __launch_bounds__(256) void proj_kernel(
    const float* __restrict__ qin, const float* __restrict__ kin, const float* __restrict__ vin,
    const float* __restrict__ Wq, const float* __restrict__ bq,
    const float* __restrict__ Wk, const float* __restrict__ bk,
    const float* __restrict__ Wv, const float* __restrict__ Wo) {
    __shared__ float sW[FF*DK];      // 16 KB
    __shared__ float sIn[64*FF];     // 32 KB
    __shared__ float sWoE[DK*3];
    __shared__ float sWv[FF*3];
    const int tid  = threadIdx.x;
    const int lane = tid & 31;       // output column
    const int wr   = tid >> 5;       // 8 warps -> 8 rows each
    const int r0r  = wr*8;
    const size_t row0 = (size_t)blockIdx.x * 64;

    if (tid < 96) {
        int d = tid / 3, f = tid - d*3;
        float s = 0.f;
        #pragma unroll
        for (int h = 0; h < 16; ++h) s += Wo[(h*DK + d)*3 + f];
        sWoE[tid] = s;
    }
    __syncthreads();
    for (int i = tid; i < FF*3; i += 256) {
        int r = i / 3, f = i - r*3;
        float s = 0.f;
        #pragma unroll
        for (int d = 0; d < DK; ++d) s = fmaf(Wv[r*DK + d], sWoE[d*3 + f], s);
        sWv[i] = s;
    }

    // =============== Q then K (same structure) ===============
    #pragma unroll 1
    for (int phase = 0; phase < 2; ++phase) {
        const float* W  = phase ? Wk : Wq;
        const float* bb = phase ? bk : bq;
        const float* in = phase ? kin : qin;
        __nv_bfloat16* gout = phase ? g_kp : g_qp;

        __syncthreads();
        for (int i = tid; i < FF*DK; i += 256) sW[i] = W[i];
        for (int i = tid; i < 2048; i += 256)
            ((float4*)sIn)[i] = ((const float4*)in)[row0*32 + i];
        __syncthreads();

        float acc[8];
        #pragma unroll
        for (int i = 0; i < 8; ++i) acc[i] = 0.f;

        #pragma unroll 2
        for (int f = 0; f < FF; f += 4) {
            float w0 = sW[(f+0)*DK + lane];
            float w1 = sW[(f+1)*DK + lane];
            float w2 = sW[(f+2)*DK + lane];
            float w3 = sW[(f+3)*DK + lane];
            #pragma unroll
            for (int r = 0; r < 8; ++r) {
                float4 x = *(float4*)&sIn[(r0r + r)*FF + f];
                acc[r] = fmaf(x.x, w0, acc[r]);
                acc[r] = fmaf(x.y, w1, acc[r]);
                acc[r] = fmaf(x.z, w2, acc[r]);
                acc[r] = fmaf(x.w, w3, acc[r]);
            }
        }

        const float bias = bb[lane];
        const float qs = phase ? 1.0f : 0.17677669529663687f;  // 1/sqrt(32) for Q
        #pragma unroll
        for (int r = 0; r < 8; ++r) {
            float v = (acc[r] + bias) * qs;
            __nv_bfloat16 h  = __float2bfloat16(v);
            __nv_bfloat16 lo = __float2bfloat16(v - __bfloat162float(h));
            size_t rr = row0 + r0r + r;
            if (phase == 0) {          // q: [hi | hi | lo]
                gout[rr*96 + lane]      = h;
                gout[rr*96 + 32 + lane] = h;
                gout[rr*96 + 64 + lane] = lo;
            } else {                   // k: [hi | lo | hi]
                gout[rr*96 + lane]      = h;
                gout[rr*96 + 32 + lane] = lo;
                gout[rr*96 + 64 + lane] = h;
            }
        }
    }

    // =============== VW (3 cols, padded to 4) ===============
    __syncthreads();
    for (int i = tid; i < 2048; i += 256)
        ((float4*)sIn)[i] = ((const float4*)vin)[row0*32 + i];
    __syncthreads();
    if (tid < 192) {
        int r = tid / 3, f = tid - r*3;
        float s0=0.f,s1=0.f,s2=0.f,s3=0.f;
        #pragma unroll 8
        for (int ff = 0; ff < FF; ff += 4) {
            s0 = fmaf(sIn[r*FF+ff+0], sWv[(ff+0)*3+f], s0);
            s1 = fmaf(sIn[r*FF+ff+1], sWv[(ff+1)*3+f], s1);
            s2 = fmaf(sIn[r*FF+ff+2], sWv[(ff+2)*3+f], s2);
            s3 = fmaf(sIn[r*FF+ff+3], sWv[(ff+3)*3+f], s3);
        }
        g_vw[(row0+r)*4 + f] = (s0+s1)+(s2+s3);
    }
}

// ---------------------------------------------------------------------------
// Flash kernel: q-tile 256/block, 8 warps x 32 q-rows (2 m-tiles each).
// HMMA bf16 K=96 combined split-GEMM; no-max softmax; fused 3-col PV.
// ---------------------------------------------------------------------------
#define RSTR 208                       // 13*16 B, odd 16B stride -> conflict-free LDSM
#define SQ_OFF 0
#define SK_OFF (256*RSTR)              // 53248
#define VW_OFF (SK_OFF + 128*RSTR)     // 79872
#define CST_OFF (VW_OFF + 2048)        // 81920
#define SMEM_BYTES (CST_OFF + 16)      // 81936

__global__ __launch_bounds__(256, 2)
void flash4_kernel(float* __restrict__ out,
                   const float* __restrict__ bv,
                   const float* __restrict__ Wo,
                   const float* __restrict__ bo) {
    extern __shared__ __align__(16) unsigned char smem[];
    float* sVW  = (float*)(smem + VW_OFF);
    float* sCST = (float*)(smem + CST_OFF);
    const int tid  = threadIdx.x;
    const int wid  = tid >> 5, lane = tid & 31;
    const size_t base = (size_t)blockIdx.y * SS;
    const int q0 = blockIdx.x * 256;
    const uint32_t sbase = smem_u32(smem);

    if (tid < 3) {
        float s = bo[tid];
        #pragma unroll
        for (int d = 0; d < DK; ++d) {
            float w = 0.f;
            #pragma unroll
            for (int h = 0; h < 16; ++h) w += Wo[(h*DK + d)*3 + tid];
            s = fmaf(bv[d], w, s);
        }
        sCST[tid] = s;
    }

    // Load Q tile: 256 rows x 192B (stride 208)
    for (int i = tid; i < 3072; i += 256) {
        int rr = i / 12, sg = i - rr*12;
        *(uint4*)(smem + SQ_OFF + rr*RSTR + sg*16) =
            *(const uint4*)((const unsigned char*)g_qp + (base + q0 + rr)*192 + sg*16);
    }
    __syncthreads();

    const int lr  = lane & 7;
    const int sel = lane >> 3;

    // Preload A fragments for 2 m-tiles (loop-invariant)
    uint32_t aF[2][6][4];
    #pragma unroll
    for (int mt = 0; mt < 2; ++mt) {
        int arow = wid*32 + mt*16 + lr + (sel & 1)*8;
        uint32_t abase = sbase + SQ_OFF + arow*RSTR + (sel >> 1)*16;
        #pragma unroll
        for (int g = 0; g < 6; ++g)
            LDSM_X4(aF[mt][g][0], aF[mt][g][1], aF[mt][g][2], aF[mt][g][3], abase + g*32);
    }

    // accumulators [mt][half]: rows wid*32 + mt*16 + (lane>>2) + half*8
    float l[2][2], Ax[2][2], Ay[2][2], Az[2][2];
    #pragma unroll
    for (int mt = 0; mt < 2; ++mt)
        #pragma unroll
        for (int hf = 0; hf < 2; ++hf) {
            l[mt][hf] = 0.f; Ax[mt][hf] = 0.f; Ay[mt][hf] = 0.f; Az[mt][hf] = 0.f;
        }
    const int qc = (lane & 3)*2;           // key col within n-tile

    for (int t = 0; t < 16; ++t) {
        const size_t kbase = base + (size_t)t * 128;
        __syncthreads();
        for (int i = tid; i < 1536; i += 256) {
            int rr = i / 12, sg = i - rr*12;
            *(uint4*)(smem + SK_OFF + rr*RSTR + sg*16) =
                *(const uint4*)((const unsigned char*)g_kp + (kbase + rr)*192 + sg*16);
        }
        if (tid < 128)
            ((float4*)sVW)[tid] = ((const float4*)g_vw)[kbase + tid];
        __syncthreads();

        #pragma unroll 4
        for (int j = 0; j < 16; ++j) {     // n-tiles of 8 key columns
            uint32_t bbase = sbase + SK_OFF + (j*8 + lr)*RSTR + sel*16;
            uint32_t bF[12];
            LDSM_X4(bF[0], bF[1], bF[2],  bF[3],  bbase);        // k-steps 0,1
            LDSM_X4(bF[4], bF[5], bF[6],  bF[7],  bbase + 64);   // k-steps 2,3
            LDSM_X4(bF[8], bF[9], bF[10], bF[11], bbase + 128);  // k-steps 4,5

            float4 va = *(float4*)&sVW[(j*8 + qc)*4];
            float4 vb = *(float4*)&sVW[(j*8 + qc + 1)*4];

            #pragma unroll
            for (int mt = 0; mt < 2; ++mt) {
                float c0=0.f, c1=0.f, c2=0.f, c3=0.f;
                #pragma unroll
                for (int s = 0; s < 6; ++s)
                    MMA16816(c0, c1, c2, c3,
                             aF[mt][s][0], aF[mt][s][1], aF[mt][s][2], aF[mt][s][3],
                             bF[2*s], bF[2*s+1]);
                float p0 = __expf(c0), p1 = __expf(c1);
                float p2 = __expf(c2), p3 = __expf(c3);
                l[mt][0] += p0 + p1;  l[mt][1] += p2 + p3;
                Ax[mt][0] = fmaf(p0, va.x, fmaf(p1, vb.x, Ax[mt][0]));
                Ay[mt][0] = fmaf(p0, va.y, fmaf(p1, vb.y, Ay[mt][0]));
                Az[mt][0] = fmaf(p0, va.z, fmaf(p1, vb.z, Az[mt][0]));
                Ax[mt][1] = fmaf(p2, va.x, fmaf(p3, vb.x, Ax[mt][1]));
                Ay[mt][1] = fmaf(p2, va.y, fmaf(p3, vb.y, Ay[mt][1]));
                Az[mt][1] = fmaf(p2, va.z, fmaf(p3, vb.z, Az[mt][1]));
            }
        }
    }

    // quad-reduce (4 lanes share each q-row) and write
    #pragma unroll
    for (int mt = 0; mt < 2; ++mt)
        #pragma unroll
        for (int hf = 0; hf < 2; ++hf) {
            #pragma unroll
            for (int o = 1; o <= 2; o <<= 1) {
                l[mt][hf]  += __shfl_xor_sync(0xffffffffu, l[mt][hf],  o);
                Ax[mt][hf] += __shfl_xor_sync(0xffffffffu, Ax[mt][hf], o);
                Ay[mt][hf] += __shfl_xor_sync(0xffffffffu, Ay[mt][hf], o);
                Az[mt][hf] += __shfl_xor_sync(0xffffffffu, Az[mt][hf], o);
            }
        }
    if ((lane & 3) == 0) {
        const float c0 = sCST[0], c1 = sCST[1], c2 = sCST[2];
        #pragma unroll
        for (int mt = 0; mt < 2; ++mt)
            #pragma unroll
            for (int hf = 0; hf < 2; ++hf) {
                size_t r = base + q0 + wid*32 + mt*16 + (lane >> 2) + hf*8;
                float inv = 1.0f / l[mt][hf];
                out[r*3 + 0] = fmaf(Ax[mt][hf], inv, c0);
                out[r*3 + 1] = fmaf(Ay[mt][hf], inv, c1);
                out[r*3 + 2] = fmaf(Az[mt][hf], inv, c2);
            }
    }
}

extern "C" void kernel_launch(void* const* d_in, const int* in_sizes, int n_in,
                              void* d_out, int out_size) {
    const float* qin = (const float*)d_in[0];
    const float* kin = (const float*)d_in[1];
    const float* vin = (const float*)d_in[2];
    const float* Wq  = (const float*)d_in[3];
    const float* bq  = (const float*)d_in[4];
    const float* Wk  = (const float*)d_in[5];
    const float* bk  = (const float*)d_in[6];
    const float* Wv  = (const float*)d_in[7];
    const float* bv  = (const float*)d_in[8];
    const float* Wo  = (const float*)d_in[9];
    const float* bo  = (const float*)d_in[10];
    float* out = (float*)d_out;

    static int configured = 0;
    if (!configured) {
        cudaFuncSetAttribute(flash4_kernel,
                             cudaFuncAttributeMaxDynamicSharedMemorySize, SMEM_BYTES);
        configured = 1;
    }
    proj_kernel<<<NROWS/64, 256>>>(qin, kin, vin, Wq, bq, Wk, bk, Wv, Wo);
    flash4_kernel<<<dim3(SS/256, BB), 256, SMEM_BYTES>>>(out, bv, Wo, bo);
}